// round 16
// baseline (speedup 1.0000x reference)
#include <cuda_runtime.h>

// TensorReduce_88536455839845 — NeRF over-compositing, R16 (convergence).
// = R15 (33.2us wall = ~7.6 TB/s effective, ~95% of HBM spec) with the
// alpha/oma algebraic fold: e = exp(-delta*density); alpha = 1-e;
// oma = e + EPS (== 1 - alpha + EPS). Saves 2 FADD/sample-pair and one link
// of the exp->scan dependency chain. Kernel is memory-floor bound; all pipes
// (FMA 21%, ALU 13%, MUFU ~35%, SHFL) have headroom.
//
// rgba:     [65536, 192, 4] f32  (d_in[0])
// distance: [65536, 192]    f32  (d_in[1])
// out:      [65536, 3]      f32

#define NR_RAYS    65536
#define NR_SAMPLES 192
#define NR_PCHUNKS 3          // chunks of 64 samples (2 consecutive per lane)

#define EPS_DIST   1e-5f
#define EPS_ALPHA  1e-8f
#define FAR_DELTA  1e4f

#define FIX_SCALE   4194304.0f          // 2^22
#define FIX_INV     (1.0f / 4194304.0f)

// sigmoid(x) = 0.5*tanh(x/2) + 0.5 ; single MUFU.TANH on sm_103a
__device__ __forceinline__ float fast_sigmoid(float x) {
    return fmaf(0.5f, __tanhf(0.5f * x), 0.5f);
}

// Warp sum via integer redux (result broadcast to all lanes).
__device__ __forceinline__ float warp_sum_fix(float v) {
    int xi = __float2int_rn(v * FIX_SCALE);
    int s;
    asm volatile("redux.sync.add.s32 %0, %1, 0xffffffff;" : "=r"(s) : "r"(xi));
    return (float)s * FIX_INV;
}

__global__ __launch_bounds__(128, 8) void composite_kernel(
    const float4* __restrict__ rgba,     // [N, S] float4
    const float*  __restrict__ dist,     // [N, S]
    float*        __restrict__ out)      // [N, 3]
{
    const unsigned FULL = 0xffffffffu;
    int gwarp = (blockIdx.x * blockDim.x + threadIdx.x) >> 5;
    int lane  = threadIdx.x & 31;
    if (gwarp >= NR_RAYS) return;

    const float4* ray_rgba  = rgba + (size_t)gwarp * NR_SAMPLES;
    const float*  ray_dist  = dist + (size_t)gwarp * NR_SAMPLES;
    const float2* ray_dist2 = (const float2*)ray_dist;

    // ---- Phase 1: ALL global loads up front ----
    // Lane owns samples s0 = 64k + 2*lane and s1 = s0 + 1.
    // d2 (= dist[s0+2]) is an L1 hit on lines the float2 loads already fetch.
    float4 v0[NR_PCHUNKS], v1[NR_PCHUNKS];
    float2 d01[NR_PCHUNKS];
    float  d2[NR_PCHUNKS];
    #pragma unroll
    for (int k = 0; k < NR_PCHUNKS; ++k) {
        int s0 = (k << 6) + (lane << 1);
        v0[k]  = __ldcs(&ray_rgba[s0]);
        v1[k]  = __ldcs(&ray_rgba[s0 + 1]);
        d01[k] = ray_dist2[(k << 5) + lane];               // (d[s0], d[s0+1])
        int s2 = s0 + 2;
        d2[k]  = ray_dist[(s2 < NR_SAMPLES) ? s2 : (NR_SAMPLES - 1)];
    }

    // ---- Phase 2: transmittance factors (no cross-lane traffic) ----
    // e = exp(-delta*density); alpha = 1-e; oma = e + EPS (= 1-alpha+EPS).
    float alpha0[NR_PCHUNKS], alpha1[NR_PCHUNKS];
    float oma0[NR_PCHUNKS];
    float P[NR_PCHUNKS];
    #pragma unroll
    for (int k = 0; k < NR_PCHUNKS; ++k) {
        float delta0 = fabsf(d01[k].y - d01[k].x);
        bool  lastS  = (k == NR_PCHUNKS - 1) && (lane == 31);   // sample 191
        float delta1 = lastS ? FAR_DELTA : fabsf(d2[k] - d01[k].y);

        float den0 = (d01[k].x < EPS_DIST) ? 0.0f : fmaxf(v0[k].w, 0.0f);
        float den1 = (d01[k].y < EPS_DIST) ? 0.0f : fmaxf(v1[k].w, 0.0f);

        float e0 = __expf(-delta0 * den0);
        float e1 = __expf(-delta1 * den1);
        alpha0[k] = 1.0f - e0;
        alpha1[k] = 1.0f - e1;
        float o0 = e0 + EPS_ALPHA;               // strictly > 0
        float o1 = e1 + EPS_ALPHA;
        oma0[k] = o0;
        P[k]    = o0 * o1;
    }

    // ---- Phase 3: 3 independent inclusive product scans (pair domain) ----
    #pragma unroll
    for (int off = 1; off < 32; off <<= 1) {
        #pragma unroll
        for (int k = 0; k < NR_PCHUNKS; ++k) {
            float t = __shfl_up_sync(FULL, P[k], off);
            if (lane >= off) P[k] *= t;
        }
    }

    // ---- Phase 4: carry chain + weighted accumulate ----
    float carry = 1.0f;
    float r_acc = 0.0f, g_acc = 0.0f, b_acc = 0.0f;
    #pragma unroll
    for (int k = 0; k < NR_PCHUNKS; ++k) {
        float e    = __shfl_up_sync(FULL, P[k], 1);
        float excl = (lane == 0) ? 1.0f : e;
        float tot  = __shfl_sync(FULL, P[k], 31);

        float trans0 = carry * excl;
        float trans1 = trans0 * oma0[k];
        float w0 = alpha0[k] * trans0;
        float w1 = alpha1[k] * trans1;

        r_acc = fmaf(w0, fast_sigmoid(v0[k].x), r_acc);
        g_acc = fmaf(w0, fast_sigmoid(v0[k].y), g_acc);
        b_acc = fmaf(w0, fast_sigmoid(v0[k].z), b_acc);
        r_acc = fmaf(w1, fast_sigmoid(v1[k].x), r_acc);
        g_acc = fmaf(w1, fast_sigmoid(v1[k].y), g_acc);
        b_acc = fmaf(w1, fast_sigmoid(v1[k].z), b_acc);

        carry *= tot;
    }

    // ---- Warp reduce via s32 redux (broadcast result) ----
    float rr = warp_sum_fix(r_acc);
    float gg = warp_sum_fix(g_acc);
    float bb = warp_sum_fix(b_acc);

    // lanes 0..2 write adjacent channels
    if (lane < 3) {
        float val = (lane == 0) ? rr : (lane == 1) ? gg : bb;
        out[(size_t)gwarp * 3 + lane] = val;
    }
}

extern "C" void kernel_launch(void* const* d_in, const int* in_sizes, int n_in,
                              void* d_out, int out_size) {
    const float4* rgba = (const float4*)d_in[0];
    const float*  dist = (const float*)d_in[1];
    float* out = (float*)d_out;

    dim3 block(128);
    dim3 grid((NR_RAYS * 32) / 128);   // 1 warp per ray, 4 warps per CTA
    composite_kernel<<<grid, block>>>(rgba, dist, out);
}

// round 17
// speedup vs baseline: 1.0019x; 1.0019x over previous
#include <cuda_runtime.h>

// TensorReduce_88536455839845 — NeRF over-compositing, R17 (convergence check).
// = R16 structure (33.2us wall = ~7.6 TB/s effective, ~95% of HBM spec) with
// 256-thread CTAs / 8192 blocks (launch_bounds(256,6) keeps the 42-reg cap
// above the kernel's 40 regs so the front-batched load burst is preserved).
// Fewer CTAs -> fewer CLC placement events / per-CTA tail contributions.
//
// rgba:     [65536, 192, 4] f32  (d_in[0])
// distance: [65536, 192]    f32  (d_in[1])
// out:      [65536, 3]      f32

#define NR_RAYS    65536
#define NR_SAMPLES 192
#define NR_PCHUNKS 3          // chunks of 64 samples (2 consecutive per lane)

#define EPS_DIST   1e-5f
#define EPS_ALPHA  1e-8f
#define FAR_DELTA  1e4f

#define FIX_SCALE   4194304.0f          // 2^22
#define FIX_INV     (1.0f / 4194304.0f)

// sigmoid(x) = 0.5*tanh(x/2) + 0.5 ; single MUFU.TANH on sm_103a
__device__ __forceinline__ float fast_sigmoid(float x) {
    return fmaf(0.5f, __tanhf(0.5f * x), 0.5f);
}

// Warp sum via integer redux (result broadcast to all lanes).
__device__ __forceinline__ float warp_sum_fix(float v) {
    int xi = __float2int_rn(v * FIX_SCALE);
    int s;
    asm volatile("redux.sync.add.s32 %0, %1, 0xffffffff;" : "=r"(s) : "r"(xi));
    return (float)s * FIX_INV;
}

__global__ __launch_bounds__(256, 6) void composite_kernel(
    const float4* __restrict__ rgba,     // [N, S] float4
    const float*  __restrict__ dist,     // [N, S]
    float*        __restrict__ out)      // [N, 3]
{
    const unsigned FULL = 0xffffffffu;
    int gwarp = (blockIdx.x * blockDim.x + threadIdx.x) >> 5;
    int lane  = threadIdx.x & 31;
    if (gwarp >= NR_RAYS) return;

    const float4* ray_rgba  = rgba + (size_t)gwarp * NR_SAMPLES;
    const float*  ray_dist  = dist + (size_t)gwarp * NR_SAMPLES;
    const float2* ray_dist2 = (const float2*)ray_dist;

    // ---- Phase 1: ALL global loads up front ----
    // Lane owns samples s0 = 64k + 2*lane and s1 = s0 + 1.
    // d2 (= dist[s0+2]) is an L1 hit on lines the float2 loads already fetch.
    float4 v0[NR_PCHUNKS], v1[NR_PCHUNKS];
    float2 d01[NR_PCHUNKS];
    float  d2[NR_PCHUNKS];
    #pragma unroll
    for (int k = 0; k < NR_PCHUNKS; ++k) {
        int s0 = (k << 6) + (lane << 1);
        v0[k]  = __ldcs(&ray_rgba[s0]);
        v1[k]  = __ldcs(&ray_rgba[s0 + 1]);
        d01[k] = ray_dist2[(k << 5) + lane];               // (d[s0], d[s0+1])
        int s2 = s0 + 2;
        d2[k]  = ray_dist[(s2 < NR_SAMPLES) ? s2 : (NR_SAMPLES - 1)];
    }

    // ---- Phase 2: transmittance factors (no cross-lane traffic) ----
    // e = exp(-delta*density); alpha = 1-e; oma = e + EPS (= 1-alpha+EPS).
    float alpha0[NR_PCHUNKS], alpha1[NR_PCHUNKS];
    float oma0[NR_PCHUNKS];
    float P[NR_PCHUNKS];
    #pragma unroll
    for (int k = 0; k < NR_PCHUNKS; ++k) {
        float delta0 = fabsf(d01[k].y - d01[k].x);
        bool  lastS  = (k == NR_PCHUNKS - 1) && (lane == 31);   // sample 191
        float delta1 = lastS ? FAR_DELTA : fabsf(d2[k] - d01[k].y);

        float den0 = (d01[k].x < EPS_DIST) ? 0.0f : fmaxf(v0[k].w, 0.0f);
        float den1 = (d01[k].y < EPS_DIST) ? 0.0f : fmaxf(v1[k].w, 0.0f);

        float e0 = __expf(-delta0 * den0);
        float e1 = __expf(-delta1 * den1);
        alpha0[k] = 1.0f - e0;
        alpha1[k] = 1.0f - e1;
        float o0 = e0 + EPS_ALPHA;               // strictly > 0
        float o1 = e1 + EPS_ALPHA;
        oma0[k] = o0;
        P[k]    = o0 * o1;
    }

    // ---- Phase 3: 3 independent inclusive product scans (pair domain) ----
    #pragma unroll
    for (int off = 1; off < 32; off <<= 1) {
        #pragma unroll
        for (int k = 0; k < NR_PCHUNKS; ++k) {
            float t = __shfl_up_sync(FULL, P[k], off);
            if (lane >= off) P[k] *= t;
        }
    }

    // ---- Phase 4: carry chain + weighted accumulate ----
    float carry = 1.0f;
    float r_acc = 0.0f, g_acc = 0.0f, b_acc = 0.0f;
    #pragma unroll
    for (int k = 0; k < NR_PCHUNKS; ++k) {
        float e    = __shfl_up_sync(FULL, P[k], 1);
        float excl = (lane == 0) ? 1.0f : e;
        float tot  = __shfl_sync(FULL, P[k], 31);

        float trans0 = carry * excl;
        float trans1 = trans0 * oma0[k];
        float w0 = alpha0[k] * trans0;
        float w1 = alpha1[k] * trans1;

        r_acc = fmaf(w0, fast_sigmoid(v0[k].x), r_acc);
        g_acc = fmaf(w0, fast_sigmoid(v0[k].y), g_acc);
        b_acc = fmaf(w0, fast_sigmoid(v0[k].z), b_acc);
        r_acc = fmaf(w1, fast_sigmoid(v1[k].x), r_acc);
        g_acc = fmaf(w1, fast_sigmoid(v1[k].y), g_acc);
        b_acc = fmaf(w1, fast_sigmoid(v1[k].z), b_acc);

        carry *= tot;
    }

    // ---- Warp reduce via s32 redux (broadcast result) ----
    float rr = warp_sum_fix(r_acc);
    float gg = warp_sum_fix(g_acc);
    float bb = warp_sum_fix(b_acc);

    // lanes 0..2 write adjacent channels
    if (lane < 3) {
        float val = (lane == 0) ? rr : (lane == 1) ? gg : bb;
        out[(size_t)gwarp * 3 + lane] = val;
    }
}

extern "C" void kernel_launch(void* const* d_in, const int* in_sizes, int n_in,
                              void* d_out, int out_size) {
    const float4* rgba = (const float4*)d_in[0];
    const float*  dist = (const float*)d_in[1];
    float* out = (float*)d_out;

    dim3 block(256);
    dim3 grid((NR_RAYS * 32) / 256);   // 1 warp per ray, 8 warps per CTA
    composite_kernel<<<grid, block>>>(rgba, dist, out);
}